// round 16
// baseline (speedup 1.0000x reference)
#include <cuda_runtime.h>
#include <cuda_bf16.h>
#include <math.h>
#include <cstdint>

typedef unsigned long long u64t;
typedef unsigned int u32t;

#define EM1 4
#define NN 64
#define FF 32
#define U1C 128
#define U2C 64
#define UAC 128
#define NT 512
#define BATCH 2048

#define NODE_PITCH 36
#define PI_PITCH 132
#define ABP 624          // byte pitch of AB / PT tiles (304 cols bf16 + pad, odd x16B)

// ---- smem regions (float indices) ----
#define R_AB_H 0         // adj+node+1 A-tile hi bf16 [64m][ABP] = 9984 fl (A..E); then pi/pj
#define R_AB_L 9984      // -> 19968
#define R_PI   0         // pi [64][132] (F-epi..G)
#define R_PJ   8448      // pj
#define R_NODE 19968     // node fp32 [64][36] = 2304 -> 22272
#define R_RED  22272     // 512 -> 22784
#define R_CAH  22784     // C A-tile hi bf16 [64][368B] = 5888 fl (B..D; h1 written in place)
#define R_CAL  28672     // -> 34560
#define R_FAH  22784     // F act hi [64][224B] = 3584 (E..F, aliases dead CA)
#define R_FAL  26368     // -> 29952
#define R_PTH  34560     // pre2T hi bf16 [64u][ABP] = 9984 fl (D-epi..E)
#define R_PTL  44544     // -> 54528
#define R_NT_H 34560     // nodeT hi bf16 [48f][144B] = 1728 fl (A..B, aliases PT)
#define R_NT_L 36288     // -> 38016
#define R_DFB  34560     // D/F double buffers: 2 x 24576B = 12288 fl (34560..46848), alias PT
#define R_CB   38016     // C double buffers: 2 x 12288B = 6144 fl (38016..44160), clear of NT
#define SMEM_FLOATS 54528
#define SMEM_BYTES (SMEM_FLOATS*4)   // 218112 B

// packed bf16 weights [split][row=u][k]
__device__ __align__(16) __nv_bfloat16 g_W2pack[2][256][160];  // D: row=e*64+u
__device__ __align__(16) __nv_bfloat16 g_WGpack[2][256][96];   // F: row=mat*128+u
__device__ __align__(16) __nv_bfloat16 g_W1pack[2][128][176];  // C: row=u, k=[W1|V1|b1|c1|0]

__device__ __forceinline__ float sigmoid_fast(float x) {
    return __fdividef(1.0f, 1.0f + __expf(-x));
}
__device__ __forceinline__ float tanh_fast(float x) {
    return 1.0f - __fdividef(2.0f, __expf(2.0f * x) + 1.0f);
}

// ---- bf16 helpers ----
__device__ __forceinline__ u32t bfpair(float a, float b) {
    u32t lo = (u32t)__bfloat16_as_ushort(__float2bfloat16_rn(a));
    u32t hi = (u32t)__bfloat16_as_ushort(__float2bfloat16_rn(b));
    return lo | (hi << 16);
}
__device__ __forceinline__ float bflo(float x) { return x - __bfloat162float(__float2bfloat16_rn(x)); }
__device__ __forceinline__ unsigned short bfh(float x) {
    return __bfloat16_as_ushort(__float2bfloat16_rn(x));
}
__device__ __forceinline__ u32t smem_u32(const void* p) {
    u32t a; asm("{ .reg .u64 t; cvta.to.shared.u64 t, %1; cvt.u32.u64 %0, t; }" : "=r"(a) : "l"(p));
    return a;
}

#define LDSM_X4(r0, r1, r2, r3, addr) \
    asm volatile("ldmatrix.sync.aligned.m8n8.x4.shared.b16 {%0,%1,%2,%3}, [%4];" \
                 : "=r"(r0), "=r"(r1), "=r"(r2), "=r"(r3) : "r"(addr))

#define MMA_BF16(c, a0, a1, a2, a3, b0, b1) \
    asm volatile("mma.sync.aligned.m16n8k16.row.col.f32.bf16.bf16.f32 " \
                 "{%0,%1,%2,%3}, {%4,%5,%6,%7}, {%8,%9}, {%0,%1,%2,%3};" \
                 : "+f"((c)[0]), "+f"((c)[1]), "+f"((c)[2]), "+f"((c)[3]) \
                 : "r"(a0), "r"(a1), "r"(a2), "r"(a3), "r"(b0), "r"(b1))

// ---- weight preconversion ----
__global__ void preconv_kernel(const float* __restrict__ W2,
                               const float* __restrict__ Wi,
                               const float* __restrict__ Wj,
                               const float* __restrict__ W1,
                               const float* __restrict__ V1,
                               const float* __restrict__ b1,
                               const float* __restrict__ c1) {
    int i = blockIdx.x * 256 + threadIdx.x;
    if (i < 256 * 160) {
        int row = i / 160, k = i % 160;
        int e = row >> 6, u = row & 63;
        float w = W2[(e * 160 + k) * 64 + u];
        __nv_bfloat16 h = __float2bfloat16_rn(w);
        g_W2pack[0][row][k] = h;
        g_W2pack[1][row][k] = __float2bfloat16_rn(w - __bfloat162float(h));
    } else if (i < 256 * 160 + 256 * 96) {
        int j = i - 256 * 160;
        int row = j / 96, k = j % 96;
        int mat = row >> 7, u = row & 127;
        float w = (mat ? Wj : Wi)[k * 128 + u];
        __nv_bfloat16 h = __float2bfloat16_rn(w);
        g_WGpack[0][row][k] = h;
        g_WGpack[1][row][k] = __float2bfloat16_rn(w - __bfloat162float(h));
    } else if (i < 256 * 160 + 256 * 96 + 128 * 176) {
        int j = i - (256 * 160 + 256 * 96);
        int u = j / 176, k = j % 176;
        float w;
        if (k < 128)      w = W1[k * 128 + u];
        else if (k < 160) w = V1[(k - 128) * 128 + u];
        else if (k < 164) w = b1[(k - 160) * 128 + u];
        else if (k == 164) w = c1[u];
        else              w = 0.0f;
        __nv_bfloat16 h = __float2bfloat16_rn(w);
        g_W1pack[0][u][k] = h;
        g_W1pack[1][u][k] = __float2bfloat16_rn(w - __bfloat162float(h));
    }
}

__global__ void __launch_bounds__(NT, 1)
encoder_kernel(const float* __restrict__ adjacency,
               const float* __restrict__ node,
               const float* __restrict__ b2, const float* __restrict__ V2,
               const float* __restrict__ c2,
               const float* __restrict__ bi, const float* __restrict__ bj,
               float* __restrict__ out)
{
    extern __shared__ float smem[];
    char* smc = (char*)smem;
    const int b = blockIdx.x;
    const int tid = threadIdx.x;
    const int wid = tid >> 5;
    const int lane = tid & 31;
    const u32t smb = smem_u32(smem);

    // ---------------- Phase A: stage all bf16 tiles ----------------------------------------
    {
        const float* adjB = adjacency + (size_t)b * (NN * NN * 5);
        for (int idx = tid; idx < NN * NN * 5; idx += NT) {
            float v = adjB[idx];
            int e = idx % 5;
            int r = idx / 5;
            if (e > 0) {
                int m = r >> 6, n = r & 63;
                int col = (e - 1) * 64 + n;
                *(unsigned short*)(smc + R_AB_H * 4 + m * ABP + col * 2) = bfh(v);
                *(unsigned short*)(smc + R_AB_L * 4 + m * ABP + col * 2) = bfh(bflo(v));
            }
        }
        const float* nodeB = node + (size_t)b * (NN * FF);
        for (int idx = tid; idx < NN * FF; idx += NT) {
            int r = idx >> 5, f = idx & 31;
            float v = nodeB[idx];
            smem[R_NODE + r * NODE_PITCH + f] = v;
            unsigned short h = bfh(v), l = bfh(bflo(v));
            *(unsigned short*)(smc + R_CAH * 4 + r * 368 + (128 + f) * 2) = h;
            *(unsigned short*)(smc + R_CAL * 4 + r * 368 + (128 + f) * 2) = l;
            *(unsigned short*)(smc + R_AB_H * 4 + r * ABP + (256 + f) * 2) = h;
            *(unsigned short*)(smc + R_AB_L * 4 + r * ABP + (256 + f) * 2) = l;
            *(unsigned short*)(smc + R_NT_H * 4 + f * 144 + r * 2) = h;
            *(unsigned short*)(smc + R_NT_L * 4 + f * 144 + r * 2) = l;
        }
        // E A-tile cols 288..303: col 288 = 1 (hi), rest/lo = 0
        for (int idx = tid; idx < 2048; idx += NT) {
            int sp = idx >> 10, j = idx & 1023, r = j >> 4, c = 288 + (j & 15);
            unsigned short v = (sp == 0 && c == 288) ? (unsigned short)0x3F80 : (unsigned short)0;
            *(unsigned short*)(smc + (sp ? R_AB_L : R_AB_H) * 4 + r * ABP + c * 2) = v;
        }
        // C A-tile cols 164..175: col 164 = 1 (hi), rest/lo = 0
        for (int idx = tid; idx < 1536; idx += NT) {
            int sp = idx / 768, j = idx % 768, r = j / 12, c = 164 + j % 12;
            unsigned short v = (sp == 0 && c == 164) ? (unsigned short)0x3F80 : (unsigned short)0;
            *(unsigned short*)(smc + (sp ? R_CAL : R_CAH) * 4 + r * 368 + c * 2) = v;
        }
        // nodeT rows 32..47: row 32 = ones (hi), rest/lo = 0
        for (int idx = tid; idx < 2048; idx += NT) {
            int sp = idx >> 10, j = idx & 1023, f = 32 + (j >> 6), n = j & 63;
            unsigned short v = (sp == 0 && f == 32) ? (unsigned short)0x3F80 : (unsigned short)0;
            *(unsigned short*)(smc + (sp ? R_NT_L : R_NT_H) * 4 + f * 144 + n * 2) = v;
        }
    }
    __syncthreads();

    // pre-stage C weight chunk 0 into C buffer 0 (region clear of nodeT; B's end barrier publishes)
    {
        const int s_sp = tid >> 8, s_row = (tid & 255) >> 1, s_c8 = (tid & 1) * 8;
        *(uint4*)(smc + R_CB * 4 + s_sp * 6144 + s_row * 48 + s_c8 * 2) =
            *(const uint4*)((const char*)g_W1pack + (size_t)(s_sp * 128 + s_row) * 352 + s_c8 * 2);
    }

    // ---------------- Phase B: an_e = adj_e @ nodeT^T via mma.sync (rowsum via ones row) ---
    {
        const int e = wid >> 2, mb = wid & 3, m0 = mb * 16;
        float acc[5][4];
        #pragma unroll
        for (int j = 0; j < 5; j++) { acc[j][0] = acc[j][1] = acc[j][2] = acc[j][3] = 0.f; }
        const int al_r = (lane & 7) + ((lane >> 3) & 1) * 8;
        const int al_c8 = (lane >> 4) * 8;
        const u32t aHi = smb + R_AB_H * 4 + (m0 + al_r) * ABP + e * 128;
        const u32t aLo = smb + R_AB_L * 4 + (m0 + al_r) * ABP + e * 128;
        const int b_r = (lane & 7) + ((lane >> 4) << 3);
        const int b_k16 = ((lane >> 3) & 1) * 16;
        const u32t ntH = smb + R_NT_H * 4 + b_r * 144 + b_k16;
        const u32t ntL = smb + R_NT_L * 4 + b_r * 144 + b_k16;
        #pragma unroll
        for (int ck = 0; ck < 4; ck++) {
            const int k0 = ck * 16;
            u32t ah0, ah1, ah2, ah3, al0, al1, al2, al3;
            LDSM_X4(ah0, ah1, ah2, ah3, aHi + (k0 + al_c8) * 2);
            LDSM_X4(al0, al1, al2, al3, aLo + (k0 + al_c8) * 2);
            #pragma unroll
            for (int t = 0; t < 3; t++) {
                u32t bh0, bh1, bh2, bh3, bl0, bl1, bl2, bl3;
                LDSM_X4(bh0, bh1, bh2, bh3, ntH + t * 2304 + k0 * 2);
                LDSM_X4(bl0, bl1, bl2, bl3, ntL + t * 2304 + k0 * 2);
                MMA_BF16(acc[2 * t], ah0, ah1, ah2, ah3, bh0, bh1);
                MMA_BF16(acc[2 * t], ah0, ah1, ah2, ah3, bl0, bl1);
                MMA_BF16(acc[2 * t], al0, al1, al2, al3, bh0, bh1);
                if (t < 2) {
                    MMA_BF16(acc[2 * t + 1], ah0, ah1, ah2, ah3, bh2, bh3);
                    MMA_BF16(acc[2 * t + 1], ah0, ah1, ah2, ah3, bl2, bl3);
                    MMA_BF16(acc[2 * t + 1], al0, al1, al2, al3, bh2, bh3);
                }
            }
        }
        // epilogue: an -> C A-tile col e*32+f ; rowsum -> col 160+e
        const int q = lane & 3, rw = lane >> 2;
        #pragma unroll
        for (int nb = 0; nb < 4; nb++) {
            int k = e * 32 + nb * 8 + 2 * q;
            int m = m0 + rw;
            *(u32t*)(smc + R_CAH * 4 + m * 368 + k * 2) = bfpair(acc[nb][0], acc[nb][1]);
            *(u32t*)(smc + R_CAL * 4 + m * 368 + k * 2) =
                bfpair(bflo(acc[nb][0]), bflo(acc[nb][1]));
            *(u32t*)(smc + R_CAH * 4 + (m + 8) * 368 + k * 2) = bfpair(acc[nb][2], acc[nb][3]);
            *(u32t*)(smc + R_CAL * 4 + (m + 8) * 368 + k * 2) =
                bfpair(bflo(acc[nb][2]), bflo(acc[nb][3]));
        }
        if (q == 0) {
            int c = (160 + e) * 2;
            int m = m0 + rw;
            *(unsigned short*)(smc + R_CAH * 4 + m * 368 + c) = bfh(acc[4][0]);
            *(unsigned short*)(smc + R_CAL * 4 + m * 368 + c) = bfh(bflo(acc[4][0]));
            *(unsigned short*)(smc + R_CAH * 4 + (m + 8) * 368 + c) = bfh(acc[4][2]);
            *(unsigned short*)(smc + R_CAL * 4 + (m + 8) * 368 + c) = bfh(bflo(acc[4][2]));
        }
    }
    __syncthreads();

    // ---------------- Phase C: h1 via mma.sync (11 chunks, double-buffered) ---------------
    {
        const int mb = wid & 3, m0 = mb * 16;
        const int us = wid >> 2, u0 = us * 32;
        float acc[4][4];
        #pragma unroll
        for (int j = 0; j < 4; j++) { acc[j][0] = acc[j][1] = acc[j][2] = acc[j][3] = 0.f; }
        const int al_r = (lane & 7) + ((lane >> 3) & 1) * 8;
        const int al_c8 = (lane >> 4) * 8;
        const u32t aHi = smb + R_CAH * 4 + (m0 + al_r) * 368;
        const u32t aLo = smb + R_CAL * 4 + (m0 + al_r) * 368;
        const int b_r = (lane & 7) + ((lane >> 4) << 3);
        const int b_k16 = ((lane >> 3) & 1) * 16;
        const int s_sp = tid >> 8, s_row = (tid & 255) >> 1, s_c8 = (tid & 1) * 8;
        const char* s_src = (const char*)g_W1pack + (size_t)(s_sp * 128 + s_row) * 352 + s_c8 * 2;
        char* s_dst = smc + R_CB * 4 + s_sp * 6144 + s_row * 48 + s_c8 * 2;
        #pragma unroll 1
        for (int ck = 0; ck < 11; ck++) {
            if (ck < 10)
                *(uint4*)(s_dst + ((ck + 1) & 1) * 12288) = *(const uint4*)(s_src + (ck + 1) * 32);
            const u32t wb = smb + R_CB * 4 + (ck & 1) * 12288;
            const int k0 = ck * 16;
            u32t ah0, ah1, ah2, ah3, al0, al1, al2, al3;
            LDSM_X4(ah0, ah1, ah2, ah3, aHi + (k0 + al_c8) * 2);
            LDSM_X4(al0, al1, al2, al3, aLo + (k0 + al_c8) * 2);
            #pragma unroll
            for (int t = 0; t < 2; t++) {
                u32t b0, b1, b2r, b3;
                LDSM_X4(b0, b1, b2r, b3, wb + (u0 + t * 16 + b_r) * 48 + b_k16);
                MMA_BF16(acc[2 * t],     ah0, ah1, ah2, ah3, b0, b1);
                MMA_BF16(acc[2 * t + 1], ah0, ah1, ah2, ah3, b2r, b3);
                MMA_BF16(acc[2 * t],     al0, al1, al2, al3, b0, b1);
                MMA_BF16(acc[2 * t + 1], al0, al1, al2, al3, b2r, b3);
            }
            #pragma unroll
            for (int t = 0; t < 2; t++) {
                u32t b0, b1, b2r, b3;
                LDSM_X4(b0, b1, b2r, b3, wb + 6144 + (u0 + t * 16 + b_r) * 48 + b_k16);
                MMA_BF16(acc[2 * t],     ah0, ah1, ah2, ah3, b0, b1);
                MMA_BF16(acc[2 * t + 1], ah0, ah1, ah2, ah3, b2r, b3);
            }
            __syncthreads();
        }
        // epilogue: h1 = tanh -> overwrite C A-tile cols 0..127
        const int q = lane & 3, rw = lane >> 2;
        #pragma unroll
        for (int j = 0; j < 4; j++) {
            int u = u0 + 8 * j + 2 * q;
            #pragma unroll
            for (int h = 0; h < 2; h++) {
                int m = m0 + rw + 8 * h;
                float t0 = tanh_fast(acc[j][2 * h]), t1 = tanh_fast(acc[j][2 * h + 1]);
                *(u32t*)(smc + R_CAH * 4 + m * 368 + u * 2) = bfpair(t0, t1);
                *(u32t*)(smc + R_CAL * 4 + m * 368 + u * 2) = bfpair(bflo(t0), bflo(t1));
            }
        }
    }
    __syncthreads();

    // ---------------- Phase D: pre2 via mma.sync (10 chunks, double-buffered) -------------
    {
        const int e = wid >> 2, nb = wid & 3, n0 = nb * 16;
        float acc[8][4];
        #pragma unroll
        for (int j = 0; j < 8; j++) { acc[j][0] = acc[j][1] = acc[j][2] = acc[j][3] = 0.f; }
        const int al_r = (lane & 7) + ((lane >> 3) & 1) * 8;
        const int al_c8 = (lane >> 4) * 8;
        const u32t aHi = smb + R_CAH * 4 + (n0 + al_r) * 368;
        const u32t aLo = smb + R_CAL * 4 + (n0 + al_r) * 368;
        const int b_r = (lane & 7) + ((lane >> 4) << 3);
        const int b_k16 = ((lane >> 3) & 1) * 16;
        const int i0 = tid, i1 = tid + 512;
        const int sp0 = i0 >> 9, j0 = i0 & 511, row0 = j0 >> 1, c80 = (j0 & 1) * 8;
        const int sp1 = i1 >> 9, j1 = i1 & 511, row1 = j1 >> 1, c81 = (j1 & 1) * 8;
        const char* src0 = (const char*)g_W2pack + (size_t)(sp0 * 256 + row0) * 320 + c80 * 2;
        const char* src1 = (const char*)g_W2pack + (size_t)(sp1 * 256 + row1) * 320 + c81 * 2;
        char* dst0 = smc + R_DFB * 4 + sp0 * 12288 + row0 * 48 + c80 * 2;
        char* dst1 = smc + R_DFB * 4 + sp1 * 12288 + row1 * 48 + c81 * 2;
        // stage chunk 0 into buffer 0
        *(uint4*)dst0 = *(const uint4*)src0;
        *(uint4*)dst1 = *(const uint4*)src1;
        __syncthreads();
        #pragma unroll 1
        for (int ck = 0; ck < 10; ck++) {
            if (ck < 9) {
                *(uint4*)(dst0 + ((ck + 1) & 1) * 24576) = *(const uint4*)(src0 + (ck + 1) * 32);
                *(uint4*)(dst1 + ((ck + 1) & 1) * 24576) = *(const uint4*)(src1 + (ck + 1) * 32);
            }
            const u32t wb = smb + R_DFB * 4 + (ck & 1) * 24576;
            const int k0 = ck * 16;
            u32t ah0, ah1, ah2, ah3, al0, al1, al2, al3;
            LDSM_X4(ah0, ah1, ah2, ah3, aHi + (k0 + al_c8) * 2);
            LDSM_X4(al0, al1, al2, al3, aLo + (k0 + al_c8) * 2);
            #pragma unroll
            for (int t = 0; t < 4; t++) {
                u32t b0, b1, b2r, b3;
                LDSM_X4(b0, b1, b2r, b3, wb + (e * 64 + t * 16 + b_r) * 48 + b_k16);
                MMA_BF16(acc[2 * t],     ah0, ah1, ah2, ah3, b0, b1);
                MMA_BF16(acc[2 * t + 1], ah0, ah1, ah2, ah3, b2r, b3);
                MMA_BF16(acc[2 * t],     al0, al1, al2, al3, b0, b1);
                MMA_BF16(acc[2 * t + 1], al0, al1, al2, al3, b2r, b3);
            }
            #pragma unroll
            for (int t = 0; t < 4; t++) {
                u32t b0, b1, b2r, b3;
                LDSM_X4(b0, b1, b2r, b3, wb + 12288 + (e * 64 + t * 16 + b_r) * 48 + b_k16);
                MMA_BF16(acc[2 * t],     ah0, ah1, ah2, ah3, b0, b1);
                MMA_BF16(acc[2 * t + 1], ah0, ah1, ah2, ah3, b2r, b3);
            }
            __syncthreads();
        }
        // epilogue: pre2T[u][n'] bf16 hi/lo (+b2), then V2/c2 extension rows (cols 256..303)
        const int q = lane & 3, rw = lane >> 2;
        char* pH = smc + R_PTH * 4;
        char* pL = smc + R_PTL * 4;
        const int np0 = e * 64 + n0 + rw;
        #pragma unroll
        for (int j = 0; j < 8; j++) {
            int u = 8 * j + 2 * q;
            float2 bb = *(const float2*)(b2 + e * 64 + u);
            float v00 = acc[j][0] + bb.x, v01 = acc[j][1] + bb.y;
            float v10 = acc[j][2] + bb.x, v11 = acc[j][3] + bb.y;
            *(unsigned short*)(pH + u * ABP + np0 * 2)             = bfh(v00);
            *(unsigned short*)(pL + u * ABP + np0 * 2)             = bfh(bflo(v00));
            *(unsigned short*)(pH + (u + 1) * ABP + np0 * 2)       = bfh(v01);
            *(unsigned short*)(pL + (u + 1) * ABP + np0 * 2)       = bfh(bflo(v01));
            *(unsigned short*)(pH + u * ABP + (np0 + 8) * 2)       = bfh(v10);
            *(unsigned short*)(pL + u * ABP + (np0 + 8) * 2)       = bfh(bflo(v10));
            *(unsigned short*)(pH + (u + 1) * ABP + (np0 + 8) * 2) = bfh(v11);
            *(unsigned short*)(pL + (u + 1) * ABP + (np0 + 8) * 2) = bfh(bflo(v11));
        }
        for (int idx = tid; idx < 64 * 48; idx += NT) {
            int u = idx / 48, c = 256 + idx % 48;
            float v = (c < 288) ? V2[(c - 256) * 64 + u] : (c == 288 ? c2[u] : 0.0f);
            *(unsigned short*)(pH + u * ABP + c * 2) = bfh(v);
            *(unsigned short*)(pL + u * ABP + c * 2) = bfh(bflo(v));
        }
    }
    __syncthreads();

    // ---------------- Phase E: h2 via ONE mma.sync GEMM, K=304 (V2+c2 folded in) ----------
    {
        const int mb = wid & 3, m0 = mb * 16;
        const int ub = wid >> 2, u0 = ub * 16;
        float acc[2][4];
        acc[0][0] = acc[0][1] = acc[0][2] = acc[0][3] = 0.f;
        acc[1][0] = acc[1][1] = acc[1][2] = acc[1][3] = 0.f;
        const int al_r = (lane & 7) + ((lane >> 3) & 1) * 8;
        const int al_c8 = (lane >> 4) * 8;
        const u32t aHi = smb + R_AB_H * 4 + (m0 + al_r) * ABP;
        const u32t aLo = smb + R_AB_L * 4 + (m0 + al_r) * ABP;
        const int b_r = (lane & 7) + ((lane >> 4) << 3);
        const int b_k16 = ((lane >> 3) & 1) * 16;
        const u32t bHi = smb + R_PTH * 4 + (u0 + b_r) * ABP + b_k16;
        const u32t bLo = smb + R_PTL * 4 + (u0 + b_r) * ABP + b_k16;
        #pragma unroll 2
        for (int ck = 0; ck < 19; ck++) {
            const int k0 = ck * 16;
            u32t ah0, ah1, ah2, ah3, al0, al1, al2, al3;
            LDSM_X4(ah0, ah1, ah2, ah3, aHi + (k0 + al_c8) * 2);
            LDSM_X4(al0, al1, al2, al3, aLo + (k0 + al_c8) * 2);
            u32t bh0, bh1, bh2, bh3, bl0, bl1, bl2, bl3;
            LDSM_X4(bh0, bh1, bh2, bh3, bHi + k0 * 2);
            LDSM_X4(bl0, bl1, bl2, bl3, bLo + k0 * 2);
            MMA_BF16(acc[0], ah0, ah1, ah2, ah3, bh0, bh1);
            MMA_BF16(acc[1], ah0, ah1, ah2, ah3, bh2, bh3);
            MMA_BF16(acc[0], ah0, ah1, ah2, ah3, bl0, bl1);
            MMA_BF16(acc[1], ah0, ah1, ah2, ah3, bl2, bl3);
            MMA_BF16(acc[0], al0, al1, al2, al3, bh0, bh1);
            MMA_BF16(acc[1], al0, al1, al2, al3, bh2, bh3);
        }
        // epilogue: tanh -> F act tiles [m][u]
        const int q = lane & 3, rw = lane >> 2;
        #pragma unroll
        for (int mh = 0; mh < 2; mh++) {
            int m = m0 + rw + mh * 8;
            #pragma unroll
            for (int t = 0; t < 2; t++) {
                int u = u0 + t * 8 + 2 * q;
                float t0 = tanh_fast(acc[t][2 * mh]);
                float t1 = tanh_fast(acc[t][2 * mh + 1]);
                *(u32t*)(smc + R_FAH * 4 + m * 224 + u * 2) = bfpair(t0, t1);
                *(u32t*)(smc + R_FAL * 4 + m * 224 + u * 2) = bfpair(bflo(t0), bflo(t1));
            }
        }
        // F act tile cols 64..95 = node
        for (int idx = tid; idx < NN * 32; idx += NT) {
            int r = idx >> 5, k = 64 + (idx & 31);
            float v = smem[R_NODE + r * NODE_PITCH + (k - 64)];
            *(unsigned short*)(smc + R_FAH * 4 + r * 224 + k * 2) = bfh(v);
            *(unsigned short*)(smc + R_FAL * 4 + r * 224 + k * 2) = bfh(bflo(v));
        }
    }
    __syncthreads();

    // ---------------- Phase F: gate pre-acts via mma.sync (6 chunks, double-buffered) -----
    {
        const int uq = wid >> 2, nb = wid & 3, n0 = nb * 16;
        float acc[8][4];
        #pragma unroll
        for (int j = 0; j < 8; j++) { acc[j][0] = acc[j][1] = acc[j][2] = acc[j][3] = 0.f; }
        const int al_r = (lane & 7) + ((lane >> 3) & 1) * 8;
        const int al_c8 = (lane >> 4) * 8;
        const u32t aHi = smb + R_FAH * 4 + (n0 + al_r) * 224;
        const u32t aLo = smb + R_FAL * 4 + (n0 + al_r) * 224;
        const int b_r = (lane & 7) + ((lane >> 4) << 3);
        const int b_k16 = ((lane >> 3) & 1) * 16;
        const int i0 = tid, i1 = tid + 512;
        const int sp0 = i0 >> 9, j0 = i0 & 511, row0 = j0 >> 1, c80 = (j0 & 1) * 8;
        const int sp1 = i1 >> 9, j1 = i1 & 511, row1 = j1 >> 1, c81 = (j1 & 1) * 8;
        const char* src0 = (const char*)g_WGpack + (size_t)(sp0 * 256 + row0) * 192 + c80 * 2;
        const char* src1 = (const char*)g_WGpack + (size_t)(sp1 * 256 + row1) * 192 + c81 * 2;
        char* dst0 = smc + R_DFB * 4 + sp0 * 12288 + row0 * 48 + c80 * 2;
        char* dst1 = smc + R_DFB * 4 + sp1 * 12288 + row1 * 48 + c81 * 2;
        // stage chunk 0 into buffer 0 (PT is dead now)
        *(uint4*)dst0 = *(const uint4*)src0;
        *(uint4*)dst1 = *(const uint4*)src1;
        __syncthreads();
        #pragma unroll 1
        for (int ck = 0; ck < 6; ck++) {
            if (ck < 5) {
                *(uint4*)(dst0 + ((ck + 1) & 1) * 24576) = *(const uint4*)(src0 + (ck + 1) * 32);
                *(uint4*)(dst1 + ((ck + 1) & 1) * 24576) = *(const uint4*)(src1 + (ck + 1) * 32);
            }
            const u32t wb = smb + R_DFB * 4 + (ck & 1) * 24576;
            const int k0 = ck * 16;
            u32t ah0, ah1, ah2, ah3, al0, al1, al2, al3;
            LDSM_X4(ah0, ah1, ah2, ah3, aHi + (k0 + al_c8) * 2);
            LDSM_X4(al0, al1, al2, al3, aLo + (k0 + al_c8) * 2);
            #pragma unroll
            for (int t = 0; t < 4; t++) {
                u32t b0, b1, b2r, b3;
                LDSM_X4(b0, b1, b2r, b3, wb + (uq * 64 + t * 16 + b_r) * 48 + b_k16);
                MMA_BF16(acc[2 * t],     ah0, ah1, ah2, ah3, b0, b1);
                MMA_BF16(acc[2 * t + 1], ah0, ah1, ah2, ah3, b2r, b3);
                MMA_BF16(acc[2 * t],     al0, al1, al2, al3, b0, b1);
                MMA_BF16(acc[2 * t + 1], al0, al1, al2, al3, b2r, b3);
            }
            #pragma unroll
            for (int t = 0; t < 4; t++) {
                u32t b0, b1, b2r, b3;
                LDSM_X4(b0, b1, b2r, b3, wb + 12288 + (uq * 64 + t * 16 + b_r) * 48 + b_k16);
                MMA_BF16(acc[2 * t],     ah0, ah1, ah2, ah3, b0, b1);
                MMA_BF16(acc[2 * t + 1], ah0, ah1, ah2, ah3, b2r, b3);
            }
            __syncthreads();
        }
        // epilogue: pi/pj (+bias) over dead AB region
        const int q = lane & 3, rw = lane >> 2;
        #pragma unroll
        for (int j = 0; j < 8; j++) {
            int up = uq * 64 + 8 * j + 2 * q;
            int mat = up >> 7, uu = up & 127;
            float2 bb = *(const float2*)((mat ? bj : bi) + uu);
            int base = (mat ? R_PJ : R_PI) + (n0 + rw) * PI_PITCH + uu;
            smem[base]                    = acc[j][0] + bb.x;
            smem[base + 1]                = acc[j][1] + bb.y;
            smem[base + 8 * PI_PITCH]     = acc[j][2] + bb.x;
            smem[base + 8 * PI_PITCH + 1] = acc[j][3] + bb.y;
        }
    }
    __syncthreads();

    // ---------------- Phase G: out[b][u] = tanh(sum_n sigmoid(pi)*tanh(pj)) ----------------
    {
        const int qg = tid >> 7, u = tid & 127;
        float s = 0.0f;
        #pragma unroll
        for (int i = 0; i < 16; i++) {
            int n = qg * 16 + i;
            float pi = smem[R_PI + n * PI_PITCH + u];
            float pj = smem[R_PJ + n * PI_PITCH + u];
            s += sigmoid_fast(pi) * tanh_fast(pj);
        }
        smem[R_RED + qg * UAC + u] = s;
    }
    __syncthreads();
    if (tid < UAC) {
        float s = smem[R_RED + tid] + smem[R_RED + UAC + tid]
                + smem[R_RED + 2 * UAC + tid] + smem[R_RED + 3 * UAC + tid];
        out[(size_t)b * UAC + tid] = tanh_fast(s);
    }
}

extern "C" void kernel_launch(void* const* d_in, const int* in_sizes, int n_in,
                              void* d_out, int out_size) {
    (void)in_sizes; (void)n_in; (void)out_size;
    const float* adjacency = (const float*)d_in[0];
    const float* node = (const float*)d_in[2];
    const float* W1 = (const float*)d_in[3];
    const float* b1 = (const float*)d_in[4];
    const float* V1 = (const float*)d_in[5];
    const float* c1 = (const float*)d_in[6];
    const float* W2 = (const float*)d_in[7];
    const float* b2 = (const float*)d_in[8];
    const float* V2 = (const float*)d_in[9];
    const float* c2 = (const float*)d_in[10];
    const float* Wi = (const float*)d_in[11];
    const float* bi = (const float*)d_in[12];
    const float* Wj = (const float*)d_in[13];
    const float* bj = (const float*)d_in[14];

    preconv_kernel<<<344, 256>>>(W2, Wi, Wj, W1, V1, b1, c1);
    cudaFuncSetAttribute(encoder_kernel,
                         cudaFuncAttributeMaxDynamicSharedMemorySize, SMEM_BYTES);
    encoder_kernel<<<BATCH, NT, SMEM_BYTES>>>(adjacency, node,
                                              b2, V2, c2,
                                              bi, bj,
                                              (float*)d_out);
}

// round 17
// speedup vs baseline: 1.1116x; 1.1116x over previous
#include <cuda_runtime.h>
#include <cuda_bf16.h>
#include <math.h>
#include <cstdint>

typedef unsigned long long u64t;
typedef unsigned int u32t;

#define EM1 4
#define NN 64
#define FF 32
#define U1C 128
#define U2C 64
#define UAC 128
#define NT 512
#define BATCH 2048

#define NODE_PITCH 36
#define PI_PITCH 132
#define ABP 624          // byte pitch of AB / PT tiles (304 cols bf16 + pad, odd x16B)

// ---- smem regions (float indices) ----
#define R_AB_H 0         // adj+node+1 A-tile hi bf16 [64m][ABP] = 9984 fl (A..E); then pi/pj
#define R_AB_L 9984      // -> 19968
#define R_PI   0         // pi [64][132] (F-epi..G)
#define R_PJ   8448      // pj
#define R_NODE 19968     // node fp32 [64][36] = 2304 -> 22272
#define R_RED  22272     // 512 -> 22784
#define R_CAH  22784     // C A-tile hi bf16 [64][368B] = 5888 fl (B..D; h1 written in place)
#define R_CAL  28672     // -> 34560
#define R_FAH  22784     // F act hi [64][224B] = 3584 (E..F, aliases dead CA)
#define R_FAL  26368     // -> 29952
#define R_PTH  34560     // pre2T hi bf16 [64u][ABP] = 9984 fl (D-epi..E)
#define R_PTL  44544     // -> 54528
#define R_NT_H 34560     // nodeT hi bf16 [48f][144B] = 1728 fl (A..B, aliases PT)
#define R_NT_L 36288     // -> 38016
#define R_DFB  34560     // D/F double buffers: 2 x 24576B = 12288 fl, alias PT (timeline-disjoint)
#define R_CB   38016     // C double buffers: 2 x 12288B = 6144 fl, clear of nodeT
#define SMEM_FLOATS 54528
#define SMEM_BYTES (SMEM_FLOATS*4)   // 218112 B

// packed bf16 weights [split][row=u][k]
__device__ __align__(16) __nv_bfloat16 g_W2pack[2][256][160];  // D: row=e*64+u
__device__ __align__(16) __nv_bfloat16 g_WGpack[2][256][96];   // F: row=mat*128+u
__device__ __align__(16) __nv_bfloat16 g_W1pack[2][128][176];  // C: row=u, k=[W1|V1|b1|c1|0]

__device__ __forceinline__ float sigmoid_fast(float x) {
    return __fdividef(1.0f, 1.0f + __expf(-x));
}
__device__ __forceinline__ float tanh_fast(float x) {
    return 1.0f - __fdividef(2.0f, __expf(2.0f * x) + 1.0f);
}

// ---- bf16 helpers ----
__device__ __forceinline__ u32t bfpair(float a, float b) {
    u32t lo = (u32t)__bfloat16_as_ushort(__float2bfloat16_rn(a));
    u32t hi = (u32t)__bfloat16_as_ushort(__float2bfloat16_rn(b));
    return lo | (hi << 16);
}
__device__ __forceinline__ float bflo(float x) { return x - __bfloat162float(__float2bfloat16_rn(x)); }
__device__ __forceinline__ unsigned short bfh(float x) {
    return __bfloat16_as_ushort(__float2bfloat16_rn(x));
}
__device__ __forceinline__ u32t smem_u32(const void* p) {
    u32t a; asm("{ .reg .u64 t; cvta.to.shared.u64 t, %1; cvt.u32.u64 %0, t; }" : "=r"(a) : "l"(p));
    return a;
}

#define LDSM_X4(r0, r1, r2, r3, addr) \
    asm volatile("ldmatrix.sync.aligned.m8n8.x4.shared.b16 {%0,%1,%2,%3}, [%4];" \
                 : "=r"(r0), "=r"(r1), "=r"(r2), "=r"(r3) : "r"(addr))

#define MMA_BF16(c, a0, a1, a2, a3, b0, b1) \
    asm volatile("mma.sync.aligned.m16n8k16.row.col.f32.bf16.bf16.f32 " \
                 "{%0,%1,%2,%3}, {%4,%5,%6,%7}, {%8,%9}, {%0,%1,%2,%3};" \
                 : "+f"((c)[0]), "+f"((c)[1]), "+f"((c)[2]), "+f"((c)[3]) \
                 : "r"(a0), "r"(a1), "r"(a2), "r"(a3), "r"(b0), "r"(b1))

// ---- weight preconversion ----
__global__ void preconv_kernel(const float* __restrict__ W2,
                               const float* __restrict__ Wi,
                               const float* __restrict__ Wj,
                               const float* __restrict__ W1,
                               const float* __restrict__ V1,
                               const float* __restrict__ b1,
                               const float* __restrict__ c1) {
    int i = blockIdx.x * 256 + threadIdx.x;
    if (i < 256 * 160) {
        int row = i / 160, k = i % 160;
        int e = row >> 6, u = row & 63;
        float w = W2[(e * 160 + k) * 64 + u];
        __nv_bfloat16 h = __float2bfloat16_rn(w);
        g_W2pack[0][row][k] = h;
        g_W2pack[1][row][k] = __float2bfloat16_rn(w - __bfloat162float(h));
    } else if (i < 256 * 160 + 256 * 96) {
        int j = i - 256 * 160;
        int row = j / 96, k = j % 96;
        int mat = row >> 7, u = row & 127;
        float w = (mat ? Wj : Wi)[k * 128 + u];
        __nv_bfloat16 h = __float2bfloat16_rn(w);
        g_WGpack[0][row][k] = h;
        g_WGpack[1][row][k] = __float2bfloat16_rn(w - __bfloat162float(h));
    } else if (i < 256 * 160 + 256 * 96 + 128 * 176) {
        int j = i - (256 * 160 + 256 * 96);
        int u = j / 176, k = j % 176;
        float w;
        if (k < 128)      w = W1[k * 128 + u];
        else if (k < 160) w = V1[(k - 128) * 128 + u];
        else if (k < 164) w = b1[(k - 160) * 128 + u];
        else if (k == 164) w = c1[u];
        else              w = 0.0f;
        __nv_bfloat16 h = __float2bfloat16_rn(w);
        g_W1pack[0][u][k] = h;
        g_W1pack[1][u][k] = __float2bfloat16_rn(w - __bfloat162float(h));
    }
}

__global__ void __launch_bounds__(NT, 1)
encoder_kernel(const float* __restrict__ adjacency,
               const float* __restrict__ node,
               const float* __restrict__ b2, const float* __restrict__ V2,
               const float* __restrict__ c2,
               const float* __restrict__ bi, const float* __restrict__ bj,
               float* __restrict__ out)
{
    extern __shared__ float smem[];
    char* smc = (char*)smem;
    const int b = blockIdx.x;
    const int tid = threadIdx.x;
    const int wid = tid >> 5;
    const int lane = tid & 31;
    const u32t smb = smem_u32(smem);

    // ---------------- Phase A: stage all bf16 tiles ----------------------------------------
    {
        const float* adjB = adjacency + (size_t)b * (NN * NN * 5);
        for (int idx = tid; idx < NN * NN * 5; idx += NT) {
            float v = adjB[idx];
            int e = idx % 5;
            int r = idx / 5;
            if (e > 0) {
                int m = r >> 6, n = r & 63;
                int col = (e - 1) * 64 + n;
                *(unsigned short*)(smc + R_AB_H * 4 + m * ABP + col * 2) = bfh(v);
                *(unsigned short*)(smc + R_AB_L * 4 + m * ABP + col * 2) = bfh(bflo(v));
            }
        }
        const float* nodeB = node + (size_t)b * (NN * FF);
        for (int idx = tid; idx < NN * FF; idx += NT) {
            int r = idx >> 5, f = idx & 31;
            float v = nodeB[idx];
            smem[R_NODE + r * NODE_PITCH + f] = v;
            unsigned short h = bfh(v), l = bfh(bflo(v));
            *(unsigned short*)(smc + R_CAH * 4 + r * 368 + (128 + f) * 2) = h;
            *(unsigned short*)(smc + R_CAL * 4 + r * 368 + (128 + f) * 2) = l;
            *(unsigned short*)(smc + R_AB_H * 4 + r * ABP + (256 + f) * 2) = h;
            *(unsigned short*)(smc + R_AB_L * 4 + r * ABP + (256 + f) * 2) = l;
            *(unsigned short*)(smc + R_NT_H * 4 + f * 144 + r * 2) = h;
            *(unsigned short*)(smc + R_NT_L * 4 + f * 144 + r * 2) = l;
        }
        // E A-tile cols 288..303: col 288 = 1 (hi), rest/lo = 0
        for (int idx = tid; idx < 2048; idx += NT) {
            int sp = idx >> 10, j = idx & 1023, r = j >> 4, c = 288 + (j & 15);
            unsigned short v = (sp == 0 && c == 288) ? (unsigned short)0x3F80 : (unsigned short)0;
            *(unsigned short*)(smc + (sp ? R_AB_L : R_AB_H) * 4 + r * ABP + c * 2) = v;
        }
        // C A-tile cols 164..175: col 164 = 1 (hi), rest/lo = 0
        for (int idx = tid; idx < 1536; idx += NT) {
            int sp = idx / 768, j = idx % 768, r = j / 12, c = 164 + j % 12;
            unsigned short v = (sp == 0 && c == 164) ? (unsigned short)0x3F80 : (unsigned short)0;
            *(unsigned short*)(smc + (sp ? R_CAL : R_CAH) * 4 + r * 368 + c * 2) = v;
        }
        // nodeT rows 32..47: row 32 = ones (hi), rest/lo = 0
        for (int idx = tid; idx < 2048; idx += NT) {
            int sp = idx >> 10, j = idx & 1023, f = 32 + (j >> 6), n = j & 63;
            unsigned short v = (sp == 0 && f == 32) ? (unsigned short)0x3F80 : (unsigned short)0;
            *(unsigned short*)(smc + (sp ? R_NT_L : R_NT_H) * 4 + f * 144 + n * 2) = v;
        }
    }

    // C staging map (1 uint4/thread/chunk)
    const int cs_sp = tid >> 8, cs_row = (tid & 255) >> 1, cs_c8 = (tid & 1) * 8;
    const char* cs_src = (const char*)g_W1pack + (size_t)(cs_sp * 128 + cs_row) * 352 + cs_c8 * 2;
    char* cs_dst = smc + R_CB * 4 + cs_sp * 6144 + cs_row * 48 + cs_c8 * 2;
    // pre-stage C chunk 0 into buf0; prefetch chunk 1 (hidden under Phase B)
    *(uint4*)cs_dst = *(const uint4*)cs_src;
    uint4 c_pf = *(const uint4*)(cs_src + 32);
    __syncthreads();

    // ---------------- Phase B: an_e = adj_e @ nodeT^T via mma.sync (rowsum via ones row) ---
    {
        const int e = wid >> 2, mb = wid & 3, m0 = mb * 16;
        float acc[5][4];
        #pragma unroll
        for (int j = 0; j < 5; j++) { acc[j][0] = acc[j][1] = acc[j][2] = acc[j][3] = 0.f; }
        const int al_r = (lane & 7) + ((lane >> 3) & 1) * 8;
        const int al_c8 = (lane >> 4) * 8;
        const u32t aHi = smb + R_AB_H * 4 + (m0 + al_r) * ABP + e * 128;
        const u32t aLo = smb + R_AB_L * 4 + (m0 + al_r) * ABP + e * 128;
        const int b_r = (lane & 7) + ((lane >> 4) << 3);
        const int b_k16 = ((lane >> 3) & 1) * 16;
        const u32t ntH = smb + R_NT_H * 4 + b_r * 144 + b_k16;
        const u32t ntL = smb + R_NT_L * 4 + b_r * 144 + b_k16;
        #pragma unroll
        for (int ck = 0; ck < 4; ck++) {
            const int k0 = ck * 16;
            u32t ah0, ah1, ah2, ah3, al0, al1, al2, al3;
            LDSM_X4(ah0, ah1, ah2, ah3, aHi + (k0 + al_c8) * 2);
            LDSM_X4(al0, al1, al2, al3, aLo + (k0 + al_c8) * 2);
            #pragma unroll
            for (int t = 0; t < 3; t++) {
                u32t bh0, bh1, bh2, bh3, bl0, bl1, bl2, bl3;
                LDSM_X4(bh0, bh1, bh2, bh3, ntH + t * 2304 + k0 * 2);
                LDSM_X4(bl0, bl1, bl2, bl3, ntL + t * 2304 + k0 * 2);
                MMA_BF16(acc[2 * t], ah0, ah1, ah2, ah3, bh0, bh1);
                MMA_BF16(acc[2 * t], ah0, ah1, ah2, ah3, bl0, bl1);
                MMA_BF16(acc[2 * t], al0, al1, al2, al3, bh0, bh1);
                if (t < 2) {
                    MMA_BF16(acc[2 * t + 1], ah0, ah1, ah2, ah3, bh2, bh3);
                    MMA_BF16(acc[2 * t + 1], ah0, ah1, ah2, ah3, bl2, bl3);
                    MMA_BF16(acc[2 * t + 1], al0, al1, al2, al3, bh2, bh3);
                }
            }
        }
        // epilogue: an -> C A-tile col e*32+f ; rowsum -> col 160+e
        const int q = lane & 3, rw = lane >> 2;
        #pragma unroll
        for (int nb = 0; nb < 4; nb++) {
            int k = e * 32 + nb * 8 + 2 * q;
            int m = m0 + rw;
            *(u32t*)(smc + R_CAH * 4 + m * 368 + k * 2) = bfpair(acc[nb][0], acc[nb][1]);
            *(u32t*)(smc + R_CAL * 4 + m * 368 + k * 2) =
                bfpair(bflo(acc[nb][0]), bflo(acc[nb][1]));
            *(u32t*)(smc + R_CAH * 4 + (m + 8) * 368 + k * 2) = bfpair(acc[nb][2], acc[nb][3]);
            *(u32t*)(smc + R_CAL * 4 + (m + 8) * 368 + k * 2) =
                bfpair(bflo(acc[nb][2]), bflo(acc[nb][3]));
        }
        if (q == 0) {
            int c = (160 + e) * 2;
            int m = m0 + rw;
            *(unsigned short*)(smc + R_CAH * 4 + m * 368 + c) = bfh(acc[4][0]);
            *(unsigned short*)(smc + R_CAL * 4 + m * 368 + c) = bfh(bflo(acc[4][0]));
            *(unsigned short*)(smc + R_CAH * 4 + (m + 8) * 368 + c) = bfh(acc[4][2]);
            *(unsigned short*)(smc + R_CAL * 4 + (m + 8) * 368 + c) = bfh(bflo(acc[4][2]));
        }
    }
    __syncthreads();

    // ---------------- Phase C: h1 (11 chunks, double-buffered + reg prefetch) -------------
    {
        const int mb = wid & 3, m0 = mb * 16;
        const int us = wid >> 2, u0 = us * 32;
        float acc[4][4];
        #pragma unroll
        for (int j = 0; j < 4; j++) { acc[j][0] = acc[j][1] = acc[j][2] = acc[j][3] = 0.f; }
        const int al_r = (lane & 7) + ((lane >> 3) & 1) * 8;
        const int al_c8 = (lane >> 4) * 8;
        const u32t aHi = smb + R_CAH * 4 + (m0 + al_r) * 368;
        const u32t aLo = smb + R_CAL * 4 + (m0 + al_r) * 368;
        const int b_r = (lane & 7) + ((lane >> 4) << 3);
        const int b_k16 = ((lane >> 3) & 1) * 16;
        #pragma unroll 1
        for (int ck = 0; ck < 11; ck++) {
            const u32t wb = smb + R_CB * 4 + (ck & 1) * 12288;
            const int k0 = ck * 16;
            u32t ah0, ah1, ah2, ah3, al0, al1, al2, al3;
            LDSM_X4(ah0, ah1, ah2, ah3, aHi + (k0 + al_c8) * 2);
            LDSM_X4(al0, al1, al2, al3, aLo + (k0 + al_c8) * 2);
            #pragma unroll
            for (int t = 0; t < 2; t++) {
                u32t b0, b1, b2r, b3;
                LDSM_X4(b0, b1, b2r, b3, wb + (u0 + t * 16 + b_r) * 48 + b_k16);
                MMA_BF16(acc[2 * t],     ah0, ah1, ah2, ah3, b0, b1);
                MMA_BF16(acc[2 * t + 1], ah0, ah1, ah2, ah3, b2r, b3);
                MMA_BF16(acc[2 * t],     al0, al1, al2, al3, b0, b1);
                MMA_BF16(acc[2 * t + 1], al0, al1, al2, al3, b2r, b3);
            }
            #pragma unroll
            for (int t = 0; t < 2; t++) {
                u32t b0, b1, b2r, b3;
                LDSM_X4(b0, b1, b2r, b3, wb + 6144 + (u0 + t * 16 + b_r) * 48 + b_k16);
                MMA_BF16(acc[2 * t],     ah0, ah1, ah2, ah3, b0, b1);
                MMA_BF16(acc[2 * t + 1], ah0, ah1, ah2, ah3, b2r, b3);
            }
            if (ck < 10) {
                *(uint4*)(cs_dst + ((ck + 1) & 1) * 12288) = c_pf;
                if (ck < 9) c_pf = *(const uint4*)(cs_src + (ck + 2) * 32);
            }
            __syncthreads();
        }
        // epilogue: h1 = tanh -> overwrite C A-tile cols 0..127
        const int q = lane & 3, rw = lane >> 2;
        #pragma unroll
        for (int j = 0; j < 4; j++) {
            int u = u0 + 8 * j + 2 * q;
            #pragma unroll
            for (int h = 0; h < 2; h++) {
                int m = m0 + rw + 8 * h;
                float t0 = tanh_fast(acc[j][2 * h]), t1 = tanh_fast(acc[j][2 * h + 1]);
                *(u32t*)(smc + R_CAH * 4 + m * 368 + u * 2) = bfpair(t0, t1);
                *(u32t*)(smc + R_CAL * 4 + m * 368 + u * 2) = bfpair(bflo(t0), bflo(t1));
            }
        }
    }
    __syncthreads();

    // ---------------- Phase D: pre2 (10 chunks, double-buffered + reg prefetch) -----------
    {
        const int e = wid >> 2, nb = wid & 3, n0 = nb * 16;
        float acc[8][4];
        #pragma unroll
        for (int j = 0; j < 8; j++) { acc[j][0] = acc[j][1] = acc[j][2] = acc[j][3] = 0.f; }
        const int al_r = (lane & 7) + ((lane >> 3) & 1) * 8;
        const int al_c8 = (lane >> 4) * 8;
        const u32t aHi = smb + R_CAH * 4 + (n0 + al_r) * 368;
        const u32t aLo = smb + R_CAL * 4 + (n0 + al_r) * 368;
        const int b_r = (lane & 7) + ((lane >> 4) << 3);
        const int b_k16 = ((lane >> 3) & 1) * 16;
        const int i0 = tid, i1 = tid + 512;
        const int sp0 = i0 >> 9, j0 = i0 & 511, row0 = j0 >> 1, c80 = (j0 & 1) * 8;
        const int sp1 = i1 >> 9, j1 = i1 & 511, row1 = j1 >> 1, c81 = (j1 & 1) * 8;
        const char* src0 = (const char*)g_W2pack + (size_t)(sp0 * 256 + row0) * 320 + c80 * 2;
        const char* src1 = (const char*)g_W2pack + (size_t)(sp1 * 256 + row1) * 320 + c81 * 2;
        char* dst0 = smc + R_DFB * 4 + sp0 * 12288 + row0 * 48 + c80 * 2;
        char* dst1 = smc + R_DFB * 4 + sp1 * 12288 + row1 * 48 + c81 * 2;
        // stage chunk 0, prefetch chunk 1
        *(uint4*)dst0 = *(const uint4*)src0;
        *(uint4*)dst1 = *(const uint4*)src1;
        uint4 pf0 = *(const uint4*)(src0 + 32);
        uint4 pf1 = *(const uint4*)(src1 + 32);
        __syncthreads();
        #pragma unroll 1
        for (int ck = 0; ck < 10; ck++) {
            const u32t wb = smb + R_DFB * 4 + (ck & 1) * 24576;
            const int k0 = ck * 16;
            u32t ah0, ah1, ah2, ah3, al0, al1, al2, al3;
            LDSM_X4(ah0, ah1, ah2, ah3, aHi + (k0 + al_c8) * 2);
            LDSM_X4(al0, al1, al2, al3, aLo + (k0 + al_c8) * 2);
            #pragma unroll
            for (int t = 0; t < 4; t++) {
                u32t b0, b1, b2r, b3;
                LDSM_X4(b0, b1, b2r, b3, wb + (e * 64 + t * 16 + b_r) * 48 + b_k16);
                MMA_BF16(acc[2 * t],     ah0, ah1, ah2, ah3, b0, b1);
                MMA_BF16(acc[2 * t + 1], ah0, ah1, ah2, ah3, b2r, b3);
                MMA_BF16(acc[2 * t],     al0, al1, al2, al3, b0, b1);
                MMA_BF16(acc[2 * t + 1], al0, al1, al2, al3, b2r, b3);
            }
            #pragma unroll
            for (int t = 0; t < 4; t++) {
                u32t b0, b1, b2r, b3;
                LDSM_X4(b0, b1, b2r, b3, wb + 12288 + (e * 64 + t * 16 + b_r) * 48 + b_k16);
                MMA_BF16(acc[2 * t],     ah0, ah1, ah2, ah3, b0, b1);
                MMA_BF16(acc[2 * t + 1], ah0, ah1, ah2, ah3, b2r, b3);
            }
            if (ck < 9) {
                *(uint4*)(dst0 + ((ck + 1) & 1) * 24576) = pf0;
                *(uint4*)(dst1 + ((ck + 1) & 1) * 24576) = pf1;
                if (ck < 8) {
                    pf0 = *(const uint4*)(src0 + (ck + 2) * 32);
                    pf1 = *(const uint4*)(src1 + (ck + 2) * 32);
                }
            }
            __syncthreads();
        }
        // epilogue: pre2T[u][n'] bf16 hi/lo (+b2), then V2/c2 extension rows (cols 256..303)
        const int q = lane & 3, rw = lane >> 2;
        char* pH = smc + R_PTH * 4;
        char* pL = smc + R_PTL * 4;
        const int np0 = e * 64 + n0 + rw;
        #pragma unroll
        for (int j = 0; j < 8; j++) {
            int u = 8 * j + 2 * q;
            float2 bb = *(const float2*)(b2 + e * 64 + u);
            float v00 = acc[j][0] + bb.x, v01 = acc[j][1] + bb.y;
            float v10 = acc[j][2] + bb.x, v11 = acc[j][3] + bb.y;
            *(unsigned short*)(pH + u * ABP + np0 * 2)             = bfh(v00);
            *(unsigned short*)(pL + u * ABP + np0 * 2)             = bfh(bflo(v00));
            *(unsigned short*)(pH + (u + 1) * ABP + np0 * 2)       = bfh(v01);
            *(unsigned short*)(pL + (u + 1) * ABP + np0 * 2)       = bfh(bflo(v01));
            *(unsigned short*)(pH + u * ABP + (np0 + 8) * 2)       = bfh(v10);
            *(unsigned short*)(pL + u * ABP + (np0 + 8) * 2)       = bfh(bflo(v10));
            *(unsigned short*)(pH + (u + 1) * ABP + (np0 + 8) * 2) = bfh(v11);
            *(unsigned short*)(pL + (u + 1) * ABP + (np0 + 8) * 2) = bfh(bflo(v11));
        }
        for (int idx = tid; idx < 64 * 48; idx += NT) {
            int u = idx / 48, c = 256 + idx % 48;
            float v = (c < 288) ? V2[(c - 256) * 64 + u] : (c == 288 ? c2[u] : 0.0f);
            *(unsigned short*)(pH + u * ABP + c * 2) = bfh(v);
            *(unsigned short*)(pL + u * ABP + c * 2) = bfh(bflo(v));
        }
    }
    __syncthreads();

    // ---------------- Phase E: h2 via ONE mma.sync GEMM, K=304 (V2+c2 folded in) ----------
    {
        const int mb = wid & 3, m0 = mb * 16;
        const int ub = wid >> 2, u0 = ub * 16;
        float acc[2][4];
        acc[0][0] = acc[0][1] = acc[0][2] = acc[0][3] = 0.f;
        acc[1][0] = acc[1][1] = acc[1][2] = acc[1][3] = 0.f;
        const int al_r = (lane & 7) + ((lane >> 3) & 1) * 8;
        const int al_c8 = (lane >> 4) * 8;
        const u32t aHi = smb + R_AB_H * 4 + (m0 + al_r) * ABP;
        const u32t aLo = smb + R_AB_L * 4 + (m0 + al_r) * ABP;
        const int b_r = (lane & 7) + ((lane >> 4) << 3);
        const int b_k16 = ((lane >> 3) & 1) * 16;
        const u32t bHi = smb + R_PTH * 4 + (u0 + b_r) * ABP + b_k16;
        const u32t bLo = smb + R_PTL * 4 + (u0 + b_r) * ABP + b_k16;
        #pragma unroll 2
        for (int ck = 0; ck < 19; ck++) {
            const int k0 = ck * 16;
            u32t ah0, ah1, ah2, ah3, al0, al1, al2, al3;
            LDSM_X4(ah0, ah1, ah2, ah3, aHi + (k0 + al_c8) * 2);
            LDSM_X4(al0, al1, al2, al3, aLo + (k0 + al_c8) * 2);
            u32t bh0, bh1, bh2, bh3, bl0, bl1, bl2, bl3;
            LDSM_X4(bh0, bh1, bh2, bh3, bHi + k0 * 2);
            LDSM_X4(bl0, bl1, bl2, bl3, bLo + k0 * 2);
            MMA_BF16(acc[0], ah0, ah1, ah2, ah3, bh0, bh1);
            MMA_BF16(acc[1], ah0, ah1, ah2, ah3, bh2, bh3);
            MMA_BF16(acc[0], ah0, ah1, ah2, ah3, bl0, bl1);
            MMA_BF16(acc[1], ah0, ah1, ah2, ah3, bl2, bl3);
            MMA_BF16(acc[0], al0, al1, al2, al3, bh0, bh1);
            MMA_BF16(acc[1], al0, al1, al2, al3, bh2, bh3);
        }
        // epilogue: tanh -> F act tiles [m][u]
        const int q = lane & 3, rw = lane >> 2;
        #pragma unroll
        for (int mh = 0; mh < 2; mh++) {
            int m = m0 + rw + mh * 8;
            #pragma unroll
            for (int t = 0; t < 2; t++) {
                int u = u0 + t * 8 + 2 * q;
                float t0 = tanh_fast(acc[t][2 * mh]);
                float t1 = tanh_fast(acc[t][2 * mh + 1]);
                *(u32t*)(smc + R_FAH * 4 + m * 224 + u * 2) = bfpair(t0, t1);
                *(u32t*)(smc + R_FAL * 4 + m * 224 + u * 2) = bfpair(bflo(t0), bflo(t1));
            }
        }
        // F act tile cols 64..95 = node
        for (int idx = tid; idx < NN * 32; idx += NT) {
            int r = idx >> 5, k = 64 + (idx & 31);
            float v = smem[R_NODE + r * NODE_PITCH + (k - 64)];
            *(unsigned short*)(smc + R_FAH * 4 + r * 224 + k * 2) = bfh(v);
            *(unsigned short*)(smc + R_FAL * 4 + r * 224 + k * 2) = bfh(bflo(v));
        }
    }
    __syncthreads();

    // ---------------- Phase F: gate pre-acts (6 chunks, double-buffered + reg prefetch) ---
    {
        const int uq = wid >> 2, nb = wid & 3, n0 = nb * 16;
        float acc[8][4];
        #pragma unroll
        for (int j = 0; j < 8; j++) { acc[j][0] = acc[j][1] = acc[j][2] = acc[j][3] = 0.f; }
        const int al_r = (lane & 7) + ((lane >> 3) & 1) * 8;
        const int al_c8 = (lane >> 4) * 8;
        const u32t aHi = smb + R_FAH * 4 + (n0 + al_r) * 224;
        const u32t aLo = smb + R_FAL * 4 + (n0 + al_r) * 224;
        const int b_r = (lane & 7) + ((lane >> 4) << 3);
        const int b_k16 = ((lane >> 3) & 1) * 16;
        const int i0 = tid, i1 = tid + 512;
        const int sp0 = i0 >> 9, j0 = i0 & 511, row0 = j0 >> 1, c80 = (j0 & 1) * 8;
        const int sp1 = i1 >> 9, j1 = i1 & 511, row1 = j1 >> 1, c81 = (j1 & 1) * 8;
        const char* src0 = (const char*)g_WGpack + (size_t)(sp0 * 256 + row0) * 192 + c80 * 2;
        const char* src1 = (const char*)g_WGpack + (size_t)(sp1 * 256 + row1) * 192 + c81 * 2;
        char* dst0 = smc + R_DFB * 4 + sp0 * 12288 + row0 * 48 + c80 * 2;
        char* dst1 = smc + R_DFB * 4 + sp1 * 12288 + row1 * 48 + c81 * 2;
        // stage chunk 0 (PT dead now), prefetch chunk 1
        *(uint4*)dst0 = *(const uint4*)src0;
        *(uint4*)dst1 = *(const uint4*)src1;
        uint4 pf0 = *(const uint4*)(src0 + 32);
        uint4 pf1 = *(const uint4*)(src1 + 32);
        __syncthreads();
        #pragma unroll 1
        for (int ck = 0; ck < 6; ck++) {
            const u32t wb = smb + R_DFB * 4 + (ck & 1) * 24576;
            const int k0 = ck * 16;
            u32t ah0, ah1, ah2, ah3, al0, al1, al2, al3;
            LDSM_X4(ah0, ah1, ah2, ah3, aHi + (k0 + al_c8) * 2);
            LDSM_X4(al0, al1, al2, al3, aLo + (k0 + al_c8) * 2);
            #pragma unroll
            for (int t = 0; t < 4; t++) {
                u32t b0, b1, b2r, b3;
                LDSM_X4(b0, b1, b2r, b3, wb + (uq * 64 + t * 16 + b_r) * 48 + b_k16);
                MMA_BF16(acc[2 * t],     ah0, ah1, ah2, ah3, b0, b1);
                MMA_BF16(acc[2 * t + 1], ah0, ah1, ah2, ah3, b2r, b3);
                MMA_BF16(acc[2 * t],     al0, al1, al2, al3, b0, b1);
                MMA_BF16(acc[2 * t + 1], al0, al1, al2, al3, b2r, b3);
            }
            #pragma unroll
            for (int t = 0; t < 4; t++) {
                u32t b0, b1, b2r, b3;
                LDSM_X4(b0, b1, b2r, b3, wb + 12288 + (uq * 64 + t * 16 + b_r) * 48 + b_k16);
                MMA_BF16(acc[2 * t],     ah0, ah1, ah2, ah3, b0, b1);
                MMA_BF16(acc[2 * t + 1], ah0, ah1, ah2, ah3, b2r, b3);
            }
            if (ck < 5) {
                *(uint4*)(dst0 + ((ck + 1) & 1) * 24576) = pf0;
                *(uint4*)(dst1 + ((ck + 1) & 1) * 24576) = pf1;
                if (ck < 4) {
                    pf0 = *(const uint4*)(src0 + (ck + 2) * 32);
                    pf1 = *(const uint4*)(src1 + (ck + 2) * 32);
                }
            }
            __syncthreads();
        }
        // epilogue: pi/pj (+bias) over dead AB region
        const int q = lane & 3, rw = lane >> 2;
        #pragma unroll
        for (int j = 0; j < 8; j++) {
            int up = uq * 64 + 8 * j + 2 * q;
            int mat = up >> 7, uu = up & 127;
            float2 bb = *(const float2*)((mat ? bj : bi) + uu);
            int base = (mat ? R_PJ : R_PI) + (n0 + rw) * PI_PITCH + uu;
            smem[base]                    = acc[j][0] + bb.x;
            smem[base + 1]                = acc[j][1] + bb.y;
            smem[base + 8 * PI_PITCH]     = acc[j][2] + bb.x;
            smem[base + 8 * PI_PITCH + 1] = acc[j][3] + bb.y;
        }
    }
    __syncthreads();

    // ---------------- Phase G: out[b][u] = tanh(sum_n sigmoid(pi)*tanh(pj)) ----------------
    {
        const int qg = tid >> 7, u = tid & 127;
        float s = 0.0f;
        #pragma unroll
        for (int i = 0; i < 16; i++) {
            int n = qg * 16 + i;
            float pi = smem[R_PI + n * PI_PITCH + u];
            float pj = smem[R_PJ + n * PI_PITCH + u];
            s += sigmoid_fast(pi) * tanh_fast(pj);
        }
        smem[R_RED + qg * UAC + u] = s;
    }
    __syncthreads();
    if (tid < UAC) {
        float s = smem[R_RED + tid] + smem[R_RED + UAC + tid]
                + smem[R_RED + 2 * UAC + tid] + smem[R_RED + 3 * UAC + tid];
        out[(size_t)b * UAC + tid] = tanh_fast(s);
    }
}

extern "C" void kernel_launch(void* const* d_in, const int* in_sizes, int n_in,
                              void* d_out, int out_size) {
    (void)in_sizes; (void)n_in; (void)out_size;
    const float* adjacency = (const float*)d_in[0];
    const float* node = (const float*)d_in[2];
    const float* W1 = (const float*)d_in[3];
    const float* b1 = (const float*)d_in[4];
    const float* V1 = (const float*)d_in[5];
    const float* c1 = (const float*)d_in[6];
    const float* W2 = (const float*)d_in[7];
    const float* b2 = (const float*)d_in[8];
    const float* V2 = (const float*)d_in[9];
    const float* c2 = (const float*)d_in[10];
    const float* Wi = (const float*)d_in[11];
    const float* bi = (const float*)d_in[12];
    const float* Wj = (const float*)d_in[13];
    const float* bj = (const float*)d_in[14];

    preconv_kernel<<<344, 256>>>(W2, Wi, Wj, W1, V1, b1, c1);
    cudaFuncSetAttribute(encoder_kernel,
                         cudaFuncAttributeMaxDynamicSharedMemorySize, SMEM_BYTES);
    encoder_kernel<<<BATCH, NT, SMEM_BYTES>>>(adjacency, node,
                                              b2, V2, c2,
                                              bi, bj,
                                              (float*)d_out);
}